// round 1
// baseline (speedup 1.0000x reference)
#include <cuda_runtime.h>
#include <math.h>

#define BB 1323          // batch == NPTS
#define DM 1024          // DMODEL
#define NTHREADS 256
#define LOG_2PI 1.8378770664093453f

__device__ __forceinline__ float softplus_f(float x) {
    // stable: max(x,0) + log1p(exp(-|x|))
    return fmaxf(x, 0.0f) + log1pf(__expf(-fabsf(x)));
}

__global__ __launch_bounds__(NTHREADS)
void mvn3d_fused_kernel(const float* __restrict__ rep,
                        const float* __restrict__ dxyz,
                        const float* __restrict__ Wm,
                        const float* __restrict__ bm,
                        const float* __restrict__ Ws,
                        const float* __restrict__ bs,
                        float* __restrict__ out)
{
    const int i   = blockIdx.x;      // batch row
    const int tid = threadIdx.x;
    const int lane = tid & 31;
    const int warp = tid >> 5;

    // -------- phase 1: 9 dot products of length 1024 --------
    float acc[9];
    #pragma unroll
    for (int a = 0; a < 9; a++) acc[a] = 0.0f;

    const float* r = rep + (size_t)i * DM;
    for (int k = tid; k < DM; k += NTHREADS) {
        float rv = r[k];
        acc[0] = fmaf(rv, Wm[k],            acc[0]);
        acc[1] = fmaf(rv, Wm[DM + k],       acc[1]);
        acc[2] = fmaf(rv, Wm[2 * DM + k],   acc[2]);
        acc[3] = fmaf(rv, Ws[k],            acc[3]);
        acc[4] = fmaf(rv, Ws[DM + k],       acc[4]);
        acc[5] = fmaf(rv, Ws[2 * DM + k],   acc[5]);
        acc[6] = fmaf(rv, Ws[3 * DM + k],   acc[6]);
        acc[7] = fmaf(rv, Ws[4 * DM + k],   acc[7]);
        acc[8] = fmaf(rv, Ws[5 * DM + k],   acc[8]);
    }

    // warp-level reduce
    #pragma unroll
    for (int a = 0; a < 9; a++) {
        #pragma unroll
        for (int off = 16; off > 0; off >>= 1)
            acc[a] += __shfl_down_sync(0xffffffffu, acc[a], off);
    }

    __shared__ float partial[8][9];
    if (lane == 0) {
        #pragma unroll
        for (int a = 0; a < 9; a++) partial[warp][a] = acc[a];
    }
    __syncthreads();

    // params: mx,my,mz, iL00, L10, iL11, L20, L21, iL22, c
    __shared__ float params[10];
    if (tid == 0) {
        float s[9];
        #pragma unroll
        for (int a = 0; a < 9; a++) {
            float v = partial[0][a];
            #pragma unroll
            for (int w = 1; w < NTHREADS / 32; w++) v += partial[w][a];
            s[a] = v;
        }
        float mx = s[0] + bm[0];
        float my = s[1] + bm[1];
        float mz = s[2] + bm[2];
        float sc0 = s[3] + bs[0];
        float sc1 = s[4] + bs[1];
        float sc2 = s[5] + bs[2];
        float sc3 = s[6] + bs[3];
        float sc4 = s[7] + bs[4];
        float sc5 = s[8] + bs[5];

        float L00 = softplus_f(sc0);
        float L10 = sc1;
        float L11 = softplus_f(sc2);
        float L20 = sc3;
        float L21 = sc4;
        float L22 = softplus_f(sc5);

        float c = -(logf(L00) + logf(L11) + logf(L22)) - 1.5f * LOG_2PI;

        params[0] = mx;
        params[1] = my;
        params[2] = mz;
        params[3] = 1.0f / L00;
        params[4] = L10;
        params[5] = 1.0f / L11;
        params[6] = L20;
        params[7] = L21;
        params[8] = 1.0f / L22;
        params[9] = c;

        // write L output block: out[B*B + i*9 .. +8] = {L00,0,0, L10,L11,0, L20,L21,L22}
        float* Lout = out + (size_t)BB * BB + (size_t)i * 9;
        Lout[0] = L00; Lout[1] = 0.0f; Lout[2] = 0.0f;
        Lout[3] = L10; Lout[4] = L11; Lout[5] = 0.0f;
        Lout[6] = L20; Lout[7] = L21; Lout[8] = L22;
    }
    __syncthreads();

    const float mx   = params[0];
    const float my   = params[1];
    const float mz   = params[2];
    const float iL00 = params[3];
    const float L10  = params[4];
    const float iL11 = params[5];
    const float L20  = params[6];
    const float L21  = params[7];
    const float iL22 = params[8];
    const float c    = params[9];

    // -------- phase 2: 1323 points for this row --------
    const float* dp = dxyz + (size_t)i * BB * 3;
    float* op = out + (size_t)i * BB;

    for (int j = tid; j < BB; j += NTHREADS) {
        float d0 = dp[3 * j + 0];
        float d1 = dp[3 * j + 1];
        float d2 = dp[3 * j + 2];

        float y0 = (d0 - mx) * iL00;
        float y1 = (d1 - my - L10 * y0) * iL11;
        float y2 = (d2 - mz - L20 * y0 - L21 * y1) * iL22;

        float M = fmaf(y0, y0, fmaf(y1, y1, y2 * y2));
        op[j] = __expf(fmaf(-0.5f, M, c));
    }
}

extern "C" void kernel_launch(void* const* d_in, const int* in_sizes, int n_in,
                              void* d_out, int out_size) {
    const float* rep  = (const float*)d_in[0];
    const float* dxyz = (const float*)d_in[1];
    const float* Wm   = (const float*)d_in[2];
    const float* bm   = (const float*)d_in[3];
    const float* Ws   = (const float*)d_in[4];
    const float* bs   = (const float*)d_in[5];
    float* out = (float*)d_out;

    mvn3d_fused_kernel<<<BB, NTHREADS>>>(rep, dxyz, Wm, bm, Ws, bs, out);
}